// round 16
// baseline (speedup 1.0000x reference)
#include <cuda_runtime.h>
#include <cuda_fp16.h>
#include <cstdint>
#include <cstddef>

#define NROWS 4096
#define ODIM  512
#define IDIM  512
#define DDIM  64

#define BM 64
#define BN 128
#define NTH 128
#define NT_W 256            // W tiles (2 i each); tile 256 = bias

#define BPITCHB 272u                       // 68 words ≡ 4 mod 32 -> ldmatrix 8-row conflict-free
#define B_STAGE (128u * BPITCHB)           // 34816 B (128 o-rows)
#define NSTAGE 3
#define SMEM_TOTAL (int)(3u * B_STAGE)     // 104448 B -> 2 CTAs/SM

__device__ float  g_xT[IDIM * NROWS];                  // x transposed: [512][4096] fp32
__device__ __half g_Wt[(size_t)IDIM * ODIM * DDIM];    // W re-laid: [i][o][d] fp16
__device__ __half g_bt[ODIM * DDIM];                   // b1 re-laid: [o][d] fp16

// ---------------- helpers ----------------
__device__ __forceinline__ uint32_t smem_u32(const void* p) {
    uint32_t a;
    asm("{ .reg .u64 t; cvta.to.shared.u64 t, %1; cvt.u32.u64 %0, t; }" : "=r"(a) : "l"(p));
    return a;
}
__device__ __forceinline__ uint32_t f2h2(float f) {   // (h,h) packed fp16x2
    uint32_t r;
    asm("{ .reg .b16 h; cvt.rn.f16.f32 h, %1; mov.b32 %0, {h, h}; }" : "=r"(r) : "f"(f));
    return r;
}
__device__ __forceinline__ uint32_t pack2(float lo, float hi) {
    __half2 h = __floats2half2_rn(lo, hi);
    return *reinterpret_cast<uint32_t*>(&h);
}
#define CP_ASYNC16(dst, src) \
    asm volatile("cp.async.cg.shared.global [%0], [%1], 16;" :: "r"(dst), "l"(src) : "memory")
#define CP_COMMIT() asm volatile("cp.async.commit_group;" ::: "memory")
#define CP_WAIT1()  asm volatile("cp.async.wait_group 1;" ::: "memory")

#define LDMX4(r0, r1, r2, r3, a) \
    asm volatile("ldmatrix.sync.aligned.m8n8.x4.shared.b16 {%0,%1,%2,%3}, [%4];" \
        : "=r"(r0), "=r"(r1), "=r"(r2), "=r"(r3) : "r"(a))
#define HMUL2(d, a, b) asm("mul.rn.f16x2 %0, %1, %2;" : "=r"(d) : "r"(a), "r"(b))

__device__ __forceinline__ void mma_f16_16816(float& c0, float& c1, float& c2, float& c3,
                                              uint32_t a0, uint32_t a1, uint32_t a2, uint32_t a3,
                                              uint32_t b0, uint32_t b1) {
    asm volatile(
        "mma.sync.aligned.m16n8k16.row.col.f32.f16.f16.f32 "
        "{%0,%1,%2,%3}, {%4,%5,%6,%7}, {%8,%9}, {%0,%1,%2,%3};"
        : "+f"(c0), "+f"(c1), "+f"(c2), "+f"(c3)
        : "r"(a0), "r"(a1), "r"(a2), "r"(a3), "r"(b0), "r"(b1));
}

// ---------------- prepass kernels ----------------
__global__ void __launch_bounds__(1024) transpose_x(const float* __restrict__ x) {
    __shared__ float t[32][33];
    const int bi = blockIdx.x * 32;
    const int bn = blockIdx.y * 32;
    t[threadIdx.y][threadIdx.x] = x[(size_t)(bn + threadIdx.y) * IDIM + bi + threadIdx.x];
    __syncthreads();
    g_xT[(size_t)(bi + threadIdx.y) * NROWS + bn + threadIdx.x] = t[threadIdx.x][threadIdx.y];
}

// W[d][i][o] fp32 -> g_Wt[i][o][d] fp16
__global__ void __launch_bounds__(1024) prep_w(const float* __restrict__ W) {
    __shared__ float sm[32][65];
    const int i  = blockIdx.x;
    const int ob = blockIdx.y * 32;
    const int tx = threadIdx.x, ty = threadIdx.y;
#pragma unroll
    for (int k = 0; k < 2; ++k) {
        int d = ty + k * 32;
        sm[tx][d] = W[(size_t)d * IDIM * ODIM + (size_t)i * ODIM + ob + tx];
    }
    __syncthreads();
    __half2 h = __floats2half2_rn(sm[ty][2 * tx], sm[ty][2 * tx + 1]);
    reinterpret_cast<__half2*>(g_Wt)[((size_t)i * ODIM + ob + ty) * 32 + tx] = h;
}

// b1[d][o] fp32 -> g_bt[o][d] fp16
__global__ void __launch_bounds__(1024) prep_b(const float* __restrict__ b1) {
    __shared__ float sm[32][65];
    const int ob = blockIdx.x * 32;
    const int tx = threadIdx.x, ty = threadIdx.y;
#pragma unroll
    for (int k = 0; k < 2; ++k) {
        int d = ty + k * 32;
        sm[tx][d] = b1[(size_t)d * ODIM + ob + tx];
    }
    __syncthreads();
    __half2 h = __floats2half2_rn(sm[ty][2 * tx], sm[ty][2 * tx + 1]);
    reinterpret_cast<__half2*>(g_bt)[(size_t)(ob + ty) * 32 + tx] = h;
}

// ---------------- main kernel: fat warps (32x64), NTH=128, 3-stage ring ----------------
__global__ void __launch_bounds__(NTH, 2) mlp_mma(
    const float* __restrict__ var,
    float* __restrict__ out)
{
    extern __shared__ __align__(128) uint8_t smem[];
    const uint32_t s0 = smem_u32(smem);

    const int tid  = threadIdx.x;
    const int lane = tid & 31;
    const int w    = tid >> 5;
    const int rowBase = blockIdx.y * BM;
    const int colBase = blockIdx.x * BN;

    const int wm = (w & 1) * 32;    // warp m-base (2 warps over M)
    const int wn = (w >> 1) * 64;   // warp n-base (2 warps over N), warp tile 32x64
    const int c  = lane & 3;
    const int g  = lane >> 2;

    // ----- this thread's 4 fragment rows -----
    int xr[4];
#pragma unroll
    for (int rr = 0; rr < 4; ++rr)
        xr[rr] = rowBase + wm + (rr >> 1) * 16 + (rr & 1) * 8 + g;

    // ----- v fragments in registers, loaded ONCE -----
    uint32_t vh[4][4][2];
#pragma unroll
    for (int rr = 0; rr < 4; ++rr) {
        const float* vp = var + (size_t)xr[rr] * DDIM;
#pragma unroll
        for (int grp = 0; grp < 4; ++grp) {
            float2 p0 = *reinterpret_cast<const float2*>(vp + grp * 16 + 2 * c);
            float2 p1 = *reinterpret_cast<const float2*>(vp + grp * 16 + 8 + 2 * c);
            vh[rr][grp][0] = pack2(p0.x, p0.y);
            vh[rr][grp][1] = pack2(p1.x, p1.y);
        }
    }

    // ----- ldmatrix per-lane base: covers nt 0..3; nt 4..7 at +32 rows -----
    const int q = lane >> 3, r8 = lane & 7;
    const uint32_t bRowLd = (uint32_t)(wn + ((q >> 1) << 3) + r8) * BPITCHB
                          + (uint32_t)(q & 1) * 16u;

    // ----- B loader (cp.async): one o-row per thread, 16 chunks -----
    const int bo = tid;             // 0..127 = o-row
    auto issueB = [&](int t) {
        if (t <= NT_W) {
            const uint32_t dstBase = s0 + (uint32_t)(t % NSTAGE) * B_STAGE + (uint32_t)bo * BPITCHB;
            if (t < NT_W) {
                const __half* p0 = g_Wt + ((size_t)(2 * t) * ODIM + colBase + bo) * DDIM;
                const __half* p1 = p0 + (size_t)ODIM * DDIM;
#pragma unroll
                for (int j = 0; j < 8; ++j) {
                    CP_ASYNC16(dstBase + (uint32_t)j * 16u,        p0 + j * 8);
                    CP_ASYNC16(dstBase + 128u + (uint32_t)j * 16u, p1 + j * 8);
                }
            } else {    // bias: k 0..63 only (upper half never read)
                const __half* p0 = g_bt + (size_t)(colBase + bo) * DDIM;
#pragma unroll
                for (int j = 0; j < 8; ++j)
                    CP_ASYNC16(dstBase + (uint32_t)j * 16u, p0 + j * 8);
            }
        }
        CP_COMMIT();   // empty group past the end keeps wait accounting exact
    };
    auto loadXf = [&](int t, float (&dst)[2][4]) {
        if (t < NT_W) {
#pragma unroll
            for (int il = 0; il < 2; ++il)
#pragma unroll
                for (int rr = 0; rr < 4; ++rr)
                    dst[il][rr] = __ldg(&g_xT[(size_t)(2 * t + il) * NROWS + xr[rr]]);
        }
    };

    float C[2][8][4];
#pragma unroll
    for (int mt = 0; mt < 2; ++mt)
#pragma unroll
        for (int nt = 0; nt < 8; ++nt)
#pragma unroll
            for (int qq = 0; qq < 4; ++qq) C[mt][nt][qq] = 0.0f;

    // ----- prologue: 2 stages in flight -----
    issueB(0); issueB(1);
    float xf[2][4];
    loadXf(0, xf);

    // ----- mainloop -----
    for (int t = 0; t <= NT_W; ++t) {
        CP_WAIT1();            // group t landed (<=1 younger pending)
        __syncthreads();       // all warps done reading stage (t-1)%3

        issueB(t + 2);         // writes stage (t+2)%3 == (t-1)%3: safe after sync

        uint32_t xh[2][4];
#pragma unroll
        for (int il = 0; il < 2; ++il)
#pragma unroll
            for (int rr = 0; rr < 4; ++rr) xh[il][rr] = f2h2(xf[il][rr]);
        loadXf(t + 1, xf);

        const uint32_t base = s0 + (uint32_t)(t % NSTAGE) * B_STAGE + bRowLd;

        if (t < NT_W) {
            // 8 k-steps; B double-buffered 16-reg sets (nt 0..7)
            uint32_t bb[2][16];
            LDMX4(bb[0][0],  bb[0][1],  bb[0][2],  bb[0][3],  base);
            LDMX4(bb[0][4],  bb[0][5],  bb[0][6],  bb[0][7],  base + 16u * BPITCHB);
            LDMX4(bb[0][8],  bb[0][9],  bb[0][10], bb[0][11], base + 32u * BPITCHB);
            LDMX4(bb[0][12], bb[0][13], bb[0][14], bb[0][15], base + 48u * BPITCHB);
#pragma unroll
            for (int kk = 0; kk < 8; ++kk) {
                const int grp = kk >> 1, il = kk & 1;
                const int cur = kk & 1;
                if (kk < 7) {
                    const int nk = kk + 1;
                    const int nks = (nk & 1) * 4 + (nk >> 1);
                    const int nxt = cur ^ 1;
                    const uint32_t nb = base + (uint32_t)nks * 32u;
                    LDMX4(bb[nxt][0],  bb[nxt][1],  bb[nxt][2],  bb[nxt][3],  nb);
                    LDMX4(bb[nxt][4],  bb[nxt][5],  bb[nxt][6],  bb[nxt][7],  nb + 16u * BPITCHB);
                    LDMX4(bb[nxt][8],  bb[nxt][9],  bb[nxt][10], bb[nxt][11], nb + 32u * BPITCHB);
                    LDMX4(bb[nxt][12], bb[nxt][13], bb[nxt][14], bb[nxt][15], nb + 48u * BPITCHB);
                }
                uint32_t a[2][4];
#pragma unroll
                for (int mt = 0; mt < 2; ++mt) {
                    HMUL2(a[mt][0], xh[il][mt * 2 + 0], vh[mt * 2 + 0][grp][0]);
                    HMUL2(a[mt][1], xh[il][mt * 2 + 1], vh[mt * 2 + 1][grp][0]);
                    HMUL2(a[mt][2], xh[il][mt * 2 + 0], vh[mt * 2 + 0][grp][1]);
                    HMUL2(a[mt][3], xh[il][mt * 2 + 1], vh[mt * 2 + 1][grp][1]);
                }
#pragma unroll
                for (int mt = 0; mt < 2; ++mt)
#pragma unroll
                    for (int nt = 0; nt < 8; ++nt)
                        mma_f16_16816(C[mt][nt][0], C[mt][nt][1], C[mt][nt][2], C[mt][nt][3],
                                      a[mt][0], a[mt][1], a[mt][2], a[mt][3],
                                      bb[cur][2 * nt], bb[cur][2 * nt + 1]);
            }
        } else {
            // bias tile: 4 real k-steps (ks 0..3), x = 1 -> a = v
#pragma unroll
            for (int ks = 0; ks < 4; ++ks) {
                uint32_t b[16];
                const uint32_t nb = base + (uint32_t)ks * 32u;
                LDMX4(b[0],  b[1],  b[2],  b[3],  nb);
                LDMX4(b[4],  b[5],  b[6],  b[7],  nb + 16u * BPITCHB);
                LDMX4(b[8],  b[9],  b[10], b[11], nb + 32u * BPITCHB);
                LDMX4(b[12], b[13], b[14], b[15], nb + 48u * BPITCHB);
                uint32_t a[2][4];
#pragma unroll
                for (int mt = 0; mt < 2; ++mt) {
                    a[mt][0] = vh[mt * 2 + 0][ks][0];
                    a[mt][1] = vh[mt * 2 + 1][ks][0];
                    a[mt][2] = vh[mt * 2 + 0][ks][1];
                    a[mt][3] = vh[mt * 2 + 1][ks][1];
                }
#pragma unroll
                for (int mt = 0; mt < 2; ++mt)
#pragma unroll
                    for (int nt = 0; nt < 8; ++nt)
                        mma_f16_16816(C[mt][nt][0], C[mt][nt][1], C[mt][nt][2], C[mt][nt][3],
                                      a[mt][0], a[mt][1], a[mt][2], a[mt][3],
                                      b[2 * nt], b[2 * nt + 1]);
            }
        }
    }

    // ----- epilogue -----
#pragma unroll
    for (int mt = 0; mt < 2; ++mt) {
        const int r0 = rowBase + wm + mt * 16 + g;
#pragma unroll
        for (int nt = 0; nt < 8; ++nt) {
            const int c0i = colBase + wn + nt * 8 + c * 2;
            float2 v0, v1;
            v0.x = C[mt][nt][0]; v0.y = C[mt][nt][1];
            v1.x = C[mt][nt][2]; v1.y = C[mt][nt][3];
            *reinterpret_cast<float2*>(&out[(size_t)r0 * ODIM + c0i]) = v0;
            *reinterpret_cast<float2*>(&out[(size_t)(r0 + 8) * ODIM + c0i]) = v1;
        }
    }
}

// ---------------- host ----------------
extern "C" void kernel_launch(void* const* d_in, const int* in_sizes, int n_in,
                              void* d_out, int out_size) {
    const float* x   = (const float*)d_in[0];   // [4096, 512]
    const float* var = (const float*)d_in[1];   // [4096, 64]
    const float* W   = (const float*)d_in[2];   // [64, 512, 512]
    const float* b1  = (const float*)d_in[3];   // [64, 512]
    float* out       = (float*)d_out;           // [4096, 512]

    {
        dim3 tb(32, 32), tg(IDIM / 32, NROWS / 32);
        transpose_x<<<tg, tb>>>(x);
    }
    {
        dim3 tb(32, 32), tg(IDIM, ODIM / 32);
        prep_w<<<tg, tb>>>(W);
    }
    {
        dim3 tb(32, 32);
        prep_b<<<ODIM / 32, tb>>>(b1);
    }

    cudaFuncSetAttribute(mlp_mma, cudaFuncAttributeMaxDynamicSharedMemorySize, SMEM_TOTAL);
    dim3 grid(ODIM / BN, NROWS / BM);   // (4, 64) = 256 CTAs, 2 per SM
    mlp_mma<<<grid, NTH, SMEM_TOTAL>>>(var, out);
}

// round 17
// speedup vs baseline: 1.5099x; 1.5099x over previous
#include <cuda_runtime.h>
#include <cuda_fp16.h>
#include <cstdint>
#include <cstddef>

#define NROWS 4096
#define ODIM  512
#define IDIM  512
#define DDIM  64

#define BM 128
#define BN 32
#define NTH 256
#define NT_W 256            // W tiles (2 i each); tile 256 = bias

#define BPITCHB 272u                       // 68 words ≡ 4 mod 32 -> ldmatrix 8-row conflict-free
#define B_STAGE (32u * BPITCHB)            // 8704 B (32 o-rows)
#define SMEM_TOTAL (int)(4u * B_STAGE)     // 34816 B -> 3 CTAs/SM fits easily

__device__ float  g_xT[IDIM * NROWS];                  // x transposed: [512][4096] fp32
__device__ __half g_Wt[(size_t)IDIM * ODIM * DDIM];    // W re-laid: [i][o][d] fp16
__device__ __half g_bt[ODIM * DDIM];                   // b1 re-laid: [o][d] fp16

// ---------------- helpers ----------------
__device__ __forceinline__ uint32_t smem_u32(const void* p) {
    uint32_t a;
    asm("{ .reg .u64 t; cvta.to.shared.u64 t, %1; cvt.u32.u64 %0, t; }" : "=r"(a) : "l"(p));
    return a;
}
__device__ __forceinline__ uint32_t f2h2(float f) {   // (h,h) packed fp16x2
    uint32_t r;
    asm("{ .reg .b16 h; cvt.rn.f16.f32 h, %1; mov.b32 %0, {h, h}; }" : "=r"(r) : "f"(f));
    return r;
}
__device__ __forceinline__ uint32_t pack2(float lo, float hi) {
    __half2 h = __floats2half2_rn(lo, hi);
    return *reinterpret_cast<uint32_t*>(&h);
}
#define CP_ASYNC16(dst, src) \
    asm volatile("cp.async.cg.shared.global [%0], [%1], 16;" :: "r"(dst), "l"(src) : "memory")
#define CP_COMMIT() asm volatile("cp.async.commit_group;" ::: "memory")
#define CP_WAIT2()  asm volatile("cp.async.wait_group 2;" ::: "memory")

#define LDMX4(r0, r1, r2, r3, a) \
    asm volatile("ldmatrix.sync.aligned.m8n8.x4.shared.b16 {%0,%1,%2,%3}, [%4];" \
        : "=r"(r0), "=r"(r1), "=r"(r2), "=r"(r3) : "r"(a))
#define HMUL2(d, a, b) asm("mul.rn.f16x2 %0, %1, %2;" : "=r"(d) : "r"(a), "r"(b))

__device__ __forceinline__ void mma_f16_16816(float& c0, float& c1, float& c2, float& c3,
                                              uint32_t a0, uint32_t a1, uint32_t a2, uint32_t a3,
                                              uint32_t b0, uint32_t b1) {
    asm volatile(
        "mma.sync.aligned.m16n8k16.row.col.f32.f16.f16.f32 "
        "{%0,%1,%2,%3}, {%4,%5,%6,%7}, {%8,%9}, {%0,%1,%2,%3};"
        : "+f"(c0), "+f"(c1), "+f"(c2), "+f"(c3)
        : "r"(a0), "r"(a1), "r"(a2), "r"(a3), "r"(b0), "r"(b1));
}

// ---------------- prepass kernels ----------------
__global__ void __launch_bounds__(1024) transpose_x(const float* __restrict__ x) {
    __shared__ float t[32][33];
    const int bi = blockIdx.x * 32;
    const int bn = blockIdx.y * 32;
    t[threadIdx.y][threadIdx.x] = x[(size_t)(bn + threadIdx.y) * IDIM + bi + threadIdx.x];
    __syncthreads();
    g_xT[(size_t)(bi + threadIdx.y) * NROWS + bn + threadIdx.x] = t[threadIdx.x][threadIdx.y];
}

// W[d][i][o] fp32 -> g_Wt[i][o][d] fp16
__global__ void __launch_bounds__(1024) prep_w(const float* __restrict__ W) {
    __shared__ float sm[32][65];
    const int i  = blockIdx.x;
    const int ob = blockIdx.y * 32;
    const int tx = threadIdx.x, ty = threadIdx.y;
#pragma unroll
    for (int k = 0; k < 2; ++k) {
        int d = ty + k * 32;
        sm[tx][d] = W[(size_t)d * IDIM * ODIM + (size_t)i * ODIM + ob + tx];
    }
    __syncthreads();
    __half2 h = __floats2half2_rn(sm[ty][2 * tx], sm[ty][2 * tx + 1]);
    reinterpret_cast<__half2*>(g_Wt)[((size_t)i * ODIM + ob + ty) * 32 + tx] = h;
}

// b1[d][o] fp32 -> g_bt[o][d] fp16
__global__ void __launch_bounds__(1024) prep_b(const float* __restrict__ b1) {
    __shared__ float sm[32][65];
    const int ob = blockIdx.x * 32;
    const int tx = threadIdx.x, ty = threadIdx.y;
#pragma unroll
    for (int k = 0; k < 2; ++k) {
        int d = ty + k * 32;
        sm[tx][d] = b1[(size_t)d * ODIM + ob + tx];
    }
    __syncthreads();
    __half2 h = __floats2half2_rn(sm[ty][2 * tx], sm[ty][2 * tx + 1]);
    reinterpret_cast<__half2*>(g_bt)[(size_t)(ob + ty) * 32 + tx] = h;
}

// ---------------- main kernel: BN=32, 3 CTAs/SM (6 warps/SMSP) ----------------
__global__ void __launch_bounds__(NTH, 3) mlp_mma(
    const float* __restrict__ var,
    float* __restrict__ out)
{
    extern __shared__ __align__(128) uint8_t smem[];
    const uint32_t s0 = smem_u32(smem);

    const int tid  = threadIdx.x;
    const int lane = tid & 31;
    const int w    = tid >> 5;
    const int rowBase = blockIdx.y * BM;
    const int colBase = blockIdx.x * BN;

    const int wm = (w & 3) * 32;    // warp m-base (4 bands over 128)
    const int wn = (w >> 2) * 16;   // warp n-half (2 halves over 32)
    const int c  = lane & 3;
    const int g  = lane >> 2;

    // ----- this thread's 4 fragment rows -----
    int xr[4];
#pragma unroll
    for (int rr = 0; rr < 4; ++rr)
        xr[rr] = rowBase + wm + (rr >> 1) * 16 + (rr & 1) * 8 + g;

    // ----- v fragments in registers, loaded ONCE (32 regs) -----
    uint32_t vh[4][4][2];
#pragma unroll
    for (int rr = 0; rr < 4; ++rr) {
        const float* vp = var + (size_t)xr[rr] * DDIM;
#pragma unroll
        for (int grp = 0; grp < 4; ++grp) {
            float2 p0 = *reinterpret_cast<const float2*>(vp + grp * 16 + 2 * c);
            float2 p1 = *reinterpret_cast<const float2*>(vp + grp * 16 + 8 + 2 * c);
            vh[rr][grp][0] = pack2(p0.x, p0.y);
            vh[rr][grp][1] = pack2(p1.x, p1.y);
        }
    }

    // ----- ldmatrix per-lane base: q selects (nt, k-octet); one x4 per k-step -----
    const int q = lane >> 3, r8 = lane & 7;
    const uint32_t bRowLd = (uint32_t)(wn + ((q & 1) << 3) + r8) * BPITCHB
                          + (uint32_t)(q >> 1) * 16u;

    // ----- B loader (cp.async): row = tid/8 (32 rows), chunk = tid%8 (32B each) -----
    const int brow = tid >> 3;
    const int bch  = tid & 7;
    const uint32_t bDst = s0 + (uint32_t)brow * BPITCHB + (uint32_t)bch * 32u;
    auto issueB = [&](int t) {
        if (t <= NT_W) {
            const uint32_t d = bDst + (uint32_t)(t & 3) * B_STAGE;
            if (t < NT_W) {
                // chunk 0-3 -> i = 2t (d 0..63); chunk 4-7 -> i = 2t+1
                const __half* p = g_Wt
                    + ((size_t)(2 * t + (bch >> 2)) * ODIM + colBase + brow) * DDIM
                    + (bch & 3) * 16;
                CP_ASYNC16(d,       p);
                CP_ASYNC16(d + 16u, p + 8);
            } else if (bch < 4) {   // bias: d 0..63 only (upper half never read)
                const __half* p = g_bt + (size_t)(colBase + brow) * DDIM + bch * 16;
                CP_ASYNC16(d,       p);
                CP_ASYNC16(d + 16u, p + 8);
            }
        }
        CP_COMMIT();   // empty group past end keeps wait accounting exact
    };
    auto loadXf = [&](int t, float (&dst)[2][4]) {
        if (t < NT_W) {
#pragma unroll
            for (int il = 0; il < 2; ++il)
#pragma unroll
                for (int rr = 0; rr < 4; ++rr)
                    dst[il][rr] = __ldg(&g_xT[(size_t)(2 * t + il) * NROWS + xr[rr]]);
        }
    };

    float C[2][2][4];   // 16 regs
#pragma unroll
    for (int mt = 0; mt < 2; ++mt)
#pragma unroll
        for (int nt = 0; nt < 2; ++nt)
#pragma unroll
            for (int qq = 0; qq < 4; ++qq) C[mt][nt][qq] = 0.0f;

    // ----- prologue: 3 stages in flight -----
    issueB(0); issueB(1); issueB(2);
    float xf[2][4];
    loadXf(0, xf);

    // ----- mainloop: one __syncthreads per tile -----
    for (int t = 0; t <= NT_W; ++t) {
        CP_WAIT2();            // group t landed (<=2 younger pending)
        __syncthreads();       // all warps done reading stage (t-1)%4

        issueB(t + 3);         // writes stage (t+3)%4 == (t-1)%4: safe after sync

        uint32_t xh[2][4];
#pragma unroll
        for (int il = 0; il < 2; ++il)
#pragma unroll
            for (int rr = 0; rr < 4; ++rr) xh[il][rr] = f2h2(xf[il][rr]);
        loadXf(t + 1, xf);

        const uint32_t base = s0 + (uint32_t)(t & 3) * B_STAGE + bRowLd;

        if (t < NT_W) {
#pragma unroll
            for (int kk = 0; kk < 8; ++kk) {
                const int grp = kk >> 1, il = kk & 1;
                const int ks = il * 4 + grp;
                uint32_t r0, r1, r2, r3;   // r0=nt0·b0, r1=nt1·b0, r2=nt0·b1, r3=nt1·b1
                LDMX4(r0, r1, r2, r3, base + (uint32_t)ks * 32u);
                uint32_t a[2][4];
#pragma unroll
                for (int mt = 0; mt < 2; ++mt) {
                    HMUL2(a[mt][0], xh[il][mt * 2 + 0], vh[mt * 2 + 0][grp][0]);
                    HMUL2(a[mt][1], xh[il][mt * 2 + 1], vh[mt * 2 + 1][grp][0]);
                    HMUL2(a[mt][2], xh[il][mt * 2 + 0], vh[mt * 2 + 0][grp][1]);
                    HMUL2(a[mt][3], xh[il][mt * 2 + 1], vh[mt * 2 + 1][grp][1]);
                }
#pragma unroll
                for (int mt = 0; mt < 2; ++mt) {
                    mma_f16_16816(C[mt][0][0], C[mt][0][1], C[mt][0][2], C[mt][0][3],
                                  a[mt][0], a[mt][1], a[mt][2], a[mt][3], r0, r2);
                    mma_f16_16816(C[mt][1][0], C[mt][1][1], C[mt][1][2], C[mt][1][3],
                                  a[mt][0], a[mt][1], a[mt][2], a[mt][3], r1, r3);
                }
            }
        } else {
            // bias tile: 4 real k-steps (ks 0..3), x = 1 -> a = v
#pragma unroll
            for (int ks = 0; ks < 4; ++ks) {
                uint32_t r0, r1, r2, r3;
                LDMX4(r0, r1, r2, r3, base + (uint32_t)ks * 32u);
                uint32_t a[2][4];
#pragma unroll
                for (int mt = 0; mt < 2; ++mt) {
                    a[mt][0] = vh[mt * 2 + 0][ks][0];
                    a[mt][1] = vh[mt * 2 + 1][ks][0];
                    a[mt][2] = vh[mt * 2 + 0][ks][1];
                    a[mt][3] = vh[mt * 2 + 1][ks][1];
                }
#pragma unroll
                for (int mt = 0; mt < 2; ++mt) {
                    mma_f16_16816(C[mt][0][0], C[mt][0][1], C[mt][0][2], C[mt][0][3],
                                  a[mt][0], a[mt][1], a[mt][2], a[mt][3], r0, r2);
                    mma_f16_16816(C[mt][1][0], C[mt][1][1], C[mt][1][2], C[mt][1][3],
                                  a[mt][0], a[mt][1], a[mt][2], a[mt][3], r1, r3);
                }
            }
        }
    }

    // ----- epilogue -----
#pragma unroll
    for (int mt = 0; mt < 2; ++mt) {
        const int r0 = rowBase + wm + mt * 16 + g;
#pragma unroll
        for (int nt = 0; nt < 2; ++nt) {
            const int c0i = colBase + wn + nt * 8 + c * 2;
            float2 v0, v1;
            v0.x = C[mt][nt][0]; v0.y = C[mt][nt][1];
            v1.x = C[mt][nt][2]; v1.y = C[mt][nt][3];
            *reinterpret_cast<float2*>(&out[(size_t)r0 * ODIM + c0i]) = v0;
            *reinterpret_cast<float2*>(&out[(size_t)(r0 + 8) * ODIM + c0i]) = v1;
        }
    }
}

// ---------------- host ----------------
extern "C" void kernel_launch(void* const* d_in, const int* in_sizes, int n_in,
                              void* d_out, int out_size) {
    const float* x   = (const float*)d_in[0];   // [4096, 512]
    const float* var = (const float*)d_in[1];   // [4096, 64]
    const float* W   = (const float*)d_in[2];   // [64, 512, 512]
    const float* b1  = (const float*)d_in[3];   // [64, 512]
    float* out       = (float*)d_out;           // [4096, 512]

    {
        dim3 tb(32, 32), tg(IDIM / 32, NROWS / 32);
        transpose_x<<<tg, tb>>>(x);
    }
    {
        dim3 tb(32, 32), tg(IDIM, ODIM / 32);
        prep_w<<<tg, tb>>>(W);
    }
    {
        dim3 tb(32, 32);
        prep_b<<<ODIM / 32, tb>>>(b1);
    }

    cudaFuncSetAttribute(mlp_mma, cudaFuncAttributeMaxDynamicSharedMemorySize, SMEM_TOTAL);
    dim3 grid(ODIM / BN, NROWS / BM);   // (16, 32) = 512 CTAs, 3 per SM
    mlp_mma<<<grid, NTH, SMEM_TOTAL>>>(var, out);
}